// round 2
// baseline (speedup 1.0000x reference)
#include <cuda_runtime.h>

// Conv2D 7x7, stride 1, pad 3. X [64,1024,1024] fp32 -> out [64,1024,1024].
// Packed-f32x2 (FFMA2) FIR-phase formulation:
//   each output keeps a 2-wide accumulator; even/odd outputs share the SAME
//   even-aligned input pairs via two pre-shifted weight-pair phases.

#define IMG 1024
#define KS 7
#define PAD 3

#define BX 32
#define BY 8
#define TX 4
#define TY 4
#define TILE_W (BX * TX)          // 128
#define TILE_H (BY * TY)          // 32
#define IN_W (TILE_W + KS - 1)    // 134
#define IN_H (TILE_H + KS - 1)    // 38
#define PITCH 136                 // floats; x4 bytes = 544, 16B-aligned rows

typedef unsigned long long ull;

__device__ __forceinline__ void ffma2(ull& d, ull a, ull b) {
    asm("fma.rn.f32x2 %0, %1, %2, %0;" : "+l"(d) : "l"(a), "l"(b));
}
__device__ __forceinline__ void unpack2(ull v, float& lo, float& hi) {
    asm("mov.b64 {%0, %1}, %2;" : "=f"(lo), "=f"(hi) : "l"(v));
}

__global__ __launch_bounds__(BX * BY, 3)
void conv7x7_kernel(const float* __restrict__ X,
                    const float* __restrict__ W,
                    float* __restrict__ out) {
    __shared__ float s_tile[IN_H * PITCH];
    __shared__ float2 s_wp[KS][2][4];   // [ky][phase][pair]

    const int tid = threadIdx.y * BX + threadIdx.x;

    // Build phase-shifted weight pairs:
    // phase0: {w0,w1},{w2,w3},{w4,w5},{w6,0}
    // phase1: {0,w0},{w1,w2},{w3,w4},{w5,w6}
    if (tid < KS * 8) {
        int ky = tid >> 3;
        int r  = tid & 7;
        int ph = r >> 2;
        int j  = r & 3;
        float lo, hi;
        if (ph == 0) {
            lo = W[ky * KS + 2 * j];
            hi = (2 * j + 1 < KS) ? W[ky * KS + 2 * j + 1] : 0.0f;
        } else {
            lo = (2 * j - 1 >= 0) ? W[ky * KS + 2 * j - 1] : 0.0f;
            hi = W[ky * KS + 2 * j];
        }
        s_wp[ky][ph][j] = make_float2(lo, hi);
    }

    const int tileX0 = blockIdx.x * TILE_W;
    const int tileY0 = blockIdx.y * TILE_H;
    const int b = blockIdx.z;
    const float* Xb = X + (size_t)b * IMG * IMG;

    // Load input tile into smem (coalesced; guarded only for border blocks)
    const int gx0 = tileX0 - PAD;
    const int gy0 = tileY0 - PAD;
    const bool interior = (gx0 >= 0) && (gy0 >= 0) &&
                          (gx0 + IN_W <= IMG) && (gy0 + IN_H <= IMG);
    if (interior) {
        for (int i = tid; i < IN_H * IN_W; i += BX * BY) {
            int r = i / IN_W;
            int c = i - r * IN_W;
            s_tile[r * PITCH + c] = __ldg(&Xb[(size_t)(gy0 + r) * IMG + (gx0 + c)]);
        }
    } else {
        for (int i = tid; i < IN_H * IN_W; i += BX * BY) {
            int r = i / IN_W;
            int c = i - r * IN_W;
            int gy = gy0 + r, gx = gx0 + c;
            float v = 0.0f;
            if (gy >= 0 && gy < IMG && gx >= 0 && gx < IMG)
                v = __ldg(&Xb[(size_t)gy * IMG + gx]);
            s_tile[r * PITCH + c] = v;
        }
    }
    __syncthreads();

    const int lx = threadIdx.x * TX;   // local output col (multiple of 4)
    const int ly = threadIdx.y * TY;   // local output row

    // acc[ry][ox]: 2-wide accumulator per output; final = lo + hi
    ull acc[TY][TX];
#pragma unroll
    for (int ry = 0; ry < TY; ++ry)
#pragma unroll
        for (int ox = 0; ox < TX; ++ox) acc[ry][ox] = 0ull;

#pragma unroll
    for (int ky = 0; ky < KS; ++ky) {
        ull wp0[4], wp1[4];
        const ull* wr0 = reinterpret_cast<const ull*>(&s_wp[ky][0][0]);
        const ull* wr1 = reinterpret_cast<const ull*>(&s_wp[ky][1][0]);
#pragma unroll
        for (int j = 0; j < 4; ++j) { wp0[j] = wr0[j]; wp1[j] = wr1[j]; }

#pragma unroll
        for (int ry = 0; ry < TY; ++ry) {
            // Window floats f[0..9] at input row (ly+ry+ky), cols lx..lx+9.
            // 16B-aligned: PITCH*4 and lx*4 are multiples of 16.
            const ull* row = reinterpret_cast<const ull*>(
                &s_tile[(ly + ry + ky) * PITCH + lx]);
            ull p0 = row[0];   // f0,f1
            ull p1 = row[1];   // f2,f3
            ull p2 = row[2];   // f4,f5
            ull p3 = row[3];   // f6,f7
            ull p4 = row[4];   // f8,f9

            // out(lx+0): even phase over p0..p3
            ffma2(acc[ry][0], p0, wp0[0]); ffma2(acc[ry][0], p1, wp0[1]);
            ffma2(acc[ry][0], p2, wp0[2]); ffma2(acc[ry][0], p3, wp0[3]);
            // out(lx+1): odd phase over p0..p3
            ffma2(acc[ry][1], p0, wp1[0]); ffma2(acc[ry][1], p1, wp1[1]);
            ffma2(acc[ry][1], p2, wp1[2]); ffma2(acc[ry][1], p3, wp1[3]);
            // out(lx+2): even phase over p1..p4
            ffma2(acc[ry][2], p1, wp0[0]); ffma2(acc[ry][2], p2, wp0[1]);
            ffma2(acc[ry][2], p3, wp0[2]); ffma2(acc[ry][2], p4, wp0[3]);
            // out(lx+3): odd phase over p1..p4
            ffma2(acc[ry][3], p1, wp1[0]); ffma2(acc[ry][3], p2, wp1[1]);
            ffma2(acc[ry][3], p3, wp1[2]); ffma2(acc[ry][3], p4, wp1[3]);
        }
    }

    // Epilogue: horizontal add + float4 stores (16B-aligned)
    float* outb = out + (size_t)b * IMG * IMG;
    const int ox0 = tileX0 + lx;
    const int oy0 = tileY0 + ly;
#pragma unroll
    for (int ry = 0; ry < TY; ++ry) {
        float4 v;
        float lo, hi;
        unpack2(acc[ry][0], lo, hi); v.x = lo + hi;
        unpack2(acc[ry][1], lo, hi); v.y = lo + hi;
        unpack2(acc[ry][2], lo, hi); v.z = lo + hi;
        unpack2(acc[ry][3], lo, hi); v.w = lo + hi;
        *reinterpret_cast<float4*>(&outb[(size_t)(oy0 + ry) * IMG + ox0]) = v;
    }
}

extern "C" void kernel_launch(void* const* d_in, const int* in_sizes, int n_in,
                              void* d_out, int out_size) {
    const float* X = (const float*)d_in[0];
    const float* W = (const float*)d_in[1];
    float* out = (float*)d_out;

    dim3 block(BX, BY);
    dim3 grid(IMG / TILE_W, IMG / TILE_H, 64);
    conv7x7_kernel<<<grid, block>>>(X, W, out);
}

// round 3
// speedup vs baseline: 1.1555x; 1.1555x over previous
#include <cuda_runtime.h>

// Conv2D 7x7, stride 1, pad 3. X [64,1024,1024] fp32 -> out [64,1024,1024].
// FFMA2 (fma.rn.f32x2) phase-trick kernel, ky-outer, vector window loads.
//   Even/odd outputs share the SAME 8B-aligned input pairs via two
//   pre-shifted weight-pair phases -> zero repacking MOVs.

#define IMG 1024
#define KS 7
#define PAD 3

#define BX 32
#define BY 8
#define TX 4
#define TY 2
#define TILE_W (BX * TX)          // 128
#define TILE_H (BY * TY)          // 16
#define IN_W (TILE_W + KS - 1)    // 134
#define IN_H (TILE_H + KS - 1)    // 22
#define PITCH 136                 // floats; 544B rows, 16B-aligned

typedef unsigned long long ull;

__device__ __forceinline__ void ffma2(ull& d, ull a, ull b) {
    asm("fma.rn.f32x2 %0, %1, %2, %0;" : "+l"(d) : "l"(a), "l"(b));
}
__device__ __forceinline__ ull pack2(float lo, float hi) {
    ull r;
    asm("mov.b64 %0, {%1, %2};" : "=l"(r) : "f"(lo), "f"(hi));
    return r;
}
__device__ __forceinline__ void unpack2(ull v, float& lo, float& hi) {
    asm("mov.b64 {%0, %1}, %2;" : "=f"(lo), "=f"(hi) : "l"(v));
}

__global__ __launch_bounds__(BX * BY, 4)
void conv7x7_kernel(const float* __restrict__ X,
                    const float* __restrict__ W,
                    float* __restrict__ out) {
    __shared__ float s_tile[IN_H * PITCH];
    __shared__ float2 s_wp[KS][2][4];   // [ky][phase][pair]

    const int tid = threadIdx.y * BX + threadIdx.x;

    // Phase-shifted weight pairs:
    // phase0: {w0,w1},{w2,w3},{w4,w5},{w6,0}
    // phase1: {0,w0},{w1,w2},{w3,w4},{w5,w6}
    if (tid < KS * 8) {
        int ky = tid >> 3;
        int r  = tid & 7;
        int ph = r >> 2;
        int j  = r & 3;
        float lo, hi;
        if (ph == 0) {
            lo = W[ky * KS + 2 * j];
            hi = (2 * j + 1 < KS) ? W[ky * KS + 2 * j + 1] : 0.0f;
        } else {
            lo = (2 * j - 1 >= 0) ? W[ky * KS + 2 * j - 1] : 0.0f;
            hi = W[ky * KS + 2 * j];
        }
        s_wp[ky][ph][j] = make_float2(lo, hi);
    }

    const int tileX0 = blockIdx.x * TILE_W;
    const int tileY0 = blockIdx.y * TILE_H;
    const int b = blockIdx.z;
    const float* Xb = X + (size_t)b * IMG * IMG;

    // Load input tile (coalesced; zero-pad at image borders)
    const int gx0 = tileX0 - PAD;
    const int gy0 = tileY0 - PAD;
    const bool interior = (gx0 >= 0) && (gy0 >= 0) &&
                          (gx0 + IN_W <= IMG) && (gy0 + IN_H <= IMG);
    if (interior) {
#pragma unroll
        for (int i = tid; i < IN_H * IN_W; i += BX * BY) {
            int r = i / IN_W;
            int c = i - r * IN_W;
            s_tile[r * PITCH + c] = __ldg(&Xb[(size_t)(gy0 + r) * IMG + (gx0 + c)]);
        }
    } else {
        for (int i = tid; i < IN_H * IN_W; i += BX * BY) {
            int r = i / IN_W;
            int c = i - r * IN_W;
            int gy = gy0 + r, gx = gx0 + c;
            float v = 0.0f;
            if (gy >= 0 && gy < IMG && gx >= 0 && gx < IMG)
                v = __ldg(&Xb[(size_t)gy * IMG + gx]);
            s_tile[r * PITCH + c] = v;
        }
    }
    __syncthreads();

    const int lx = threadIdx.x * TX;   // output col (multiple of 4 -> 16B aligned)
    const int ly = threadIdx.y * TY;   // output row

    ull acc[TY][TX];
#pragma unroll
    for (int ry = 0; ry < TY; ++ry)
#pragma unroll
        for (int ox = 0; ox < TX; ++ox) acc[ry][ox] = 0ull;

#pragma unroll
    for (int ky = 0; ky < KS; ++ky) {
        // 8 weight pairs for this ky (broadcast LDS.64)
        ull wp0[4], wp1[4];
        const ull* wr0 = reinterpret_cast<const ull*>(&s_wp[ky][0][0]);
        const ull* wr1 = reinterpret_cast<const ull*>(&s_wp[ky][1][0]);
#pragma unroll
        for (int j = 0; j < 4; ++j) { wp0[j] = wr0[j]; wp1[j] = wr1[j]; }

#pragma unroll
        for (int ry = 0; ry < TY; ++ry) {
            // Window f[0..9] at input row (ly+ry+ky), cols lx..lx+9 (16B aligned)
            const float* rowp = &s_tile[(ly + ry + ky) * PITCH + lx];
            float4 A = *reinterpret_cast<const float4*>(rowp);
            float4 Bv = *reinterpret_cast<const float4*>(rowp + 4);
            float2 C = *reinterpret_cast<const float2*>(rowp + 8);

            ull p0 = pack2(A.x, A.y);
            ull p1 = pack2(A.z, A.w);
            ull p2 = pack2(Bv.x, Bv.y);
            ull p3 = pack2(Bv.z, Bv.w);
            ull p4 = pack2(C.x, C.y);

            // out(lx+0): even phase over p0..p3
            ffma2(acc[ry][0], p0, wp0[0]); ffma2(acc[ry][0], p1, wp0[1]);
            ffma2(acc[ry][0], p2, wp0[2]); ffma2(acc[ry][0], p3, wp0[3]);
            // out(lx+1): odd phase over p0..p3
            ffma2(acc[ry][1], p0, wp1[0]); ffma2(acc[ry][1], p1, wp1[1]);
            ffma2(acc[ry][1], p2, wp1[2]); ffma2(acc[ry][1], p3, wp1[3]);
            // out(lx+2): even phase over p1..p4
            ffma2(acc[ry][2], p1, wp0[0]); ffma2(acc[ry][2], p2, wp0[1]);
            ffma2(acc[ry][2], p3, wp0[2]); ffma2(acc[ry][2], p4, wp0[3]);
            // out(lx+3): odd phase over p1..p4
            ffma2(acc[ry][3], p1, wp1[0]); ffma2(acc[ry][3], p2, wp1[1]);
            ffma2(acc[ry][3], p3, wp1[2]); ffma2(acc[ry][3], p4, wp1[3]);
        }
    }

    // Epilogue: horizontal add + float4 store
    float* outb = out + (size_t)b * IMG * IMG;
    const int ox0 = tileX0 + lx;
    const int oy0 = tileY0 + ly;
#pragma unroll
    for (int ry = 0; ry < TY; ++ry) {
        float4 v;
        float lo, hi;
        unpack2(acc[ry][0], lo, hi); v.x = lo + hi;
        unpack2(acc[ry][1], lo, hi); v.y = lo + hi;
        unpack2(acc[ry][2], lo, hi); v.z = lo + hi;
        unpack2(acc[ry][3], lo, hi); v.w = lo + hi;
        *reinterpret_cast<float4*>(&outb[(size_t)(oy0 + ry) * IMG + ox0]) = v;
    }
}

extern "C" void kernel_launch(void* const* d_in, const int* in_sizes, int n_in,
                              void* d_out, int out_size) {
    const float* X = (const float*)d_in[0];
    const float* W = (const float*)d_in[1];
    float* out = (float*)d_out;

    dim3 block(BX, BY);
    dim3 grid(IMG / TILE_W, IMG / TILE_H, 64);
    conv7x7_kernel<<<grid, block>>>(X, W, out);
}

// round 4
// speedup vs baseline: 2.0278x; 1.7550x over previous
#include <cuda_runtime.h>

// Conv2D 7x7, stride 1, pad 3. X [64,1024,1024] fp32 -> out [64,1024,1024].
// cp.async double-buffered chunk pipeline + FFMA2 (fma.rn.f32x2) phase trick.
// All global loads, smem stores, smem window loads are 16B-aligned.

#define IMG 1024
#define KS 7
#define PAD 3

#define BX 32
#define BY 8
#define TX 4
#define TY 4
#define TILE_W (BX * TX)           // 128
#define CHUNK_H (BY * TY)          // 32 output rows per chunk
#define YGROUPS 2
#define YSPAN (IMG / YGROUPS)      // 512 rows per block
#define NCHUNK (YSPAN / CHUNK_H)   // 16

#define IN_H (CHUNK_H + KS - 1)    // 38 input rows per chunk
#define PITCH 136                  // floats per smem row (544B, 16B-aligned)
#define ROW4 34                    // float4 per row (136/4)
#define TOT4 (IN_H * ROW4)         // 1292 float4 per chunk

typedef unsigned long long ull;

__device__ __forceinline__ void ffma2(ull& d, ull a, ull b) {
    asm("fma.rn.f32x2 %0, %1, %2, %0;" : "+l"(d) : "l"(a), "l"(b));
}
__device__ __forceinline__ ull pack2(float lo, float hi) {
    ull r;
    asm("mov.b64 %0, {%1, %2};" : "=l"(r) : "f"(lo), "f"(hi));
    return r;
}
__device__ __forceinline__ void unpack2(ull v, float& lo, float& hi) {
    asm("mov.b64 {%0, %1}, %2;" : "=f"(lo), "=f"(hi) : "l"(v));
}
template <int N>
__device__ __forceinline__ void cp_wait_group() {
    asm volatile("cp.async.wait_group %0;" :: "n"(N));
}

// Issue cp.async loads for one 38-row chunk into sbuf.
// gx0 = tileX0 - 4 (16B aligned), gy0 = chunk_y0 - 3.
__device__ __forceinline__ void issue_chunk(float* sbuf, const float* Xb,
                                            int gx0, int gy0, int tid) {
    for (int i = tid; i < TOT4; i += BX * BY) {
        int r  = i / ROW4;
        int c4 = i - r * ROW4;
        int gy = gy0 + r;
        int gx = gx0 + c4 * 4;
        bool ok = (gy >= 0) && (gy < IMG) && (gx >= 0) && (gx < IMG);
        const float* src = ok ? (Xb + (size_t)gy * IMG + gx) : Xb;
        unsigned ss = ok ? 16u : 0u;
        unsigned saddr = (unsigned)__cvta_generic_to_shared(&sbuf[r * PITCH + c4 * 4]);
        asm volatile("cp.async.cg.shared.global [%0], [%1], 16, %2;"
                     :: "r"(saddr), "l"(src), "r"(ss));
    }
    asm volatile("cp.async.commit_group;");
}

__global__ __launch_bounds__(BX * BY, 3)
void conv7x7_kernel(const float* __restrict__ X,
                    const float* __restrict__ W,
                    float* __restrict__ out) {
    __shared__ float s_buf[2][IN_H * PITCH];
    __shared__ float2 s_wp[KS][2][4];   // [ky][phase][pair]

    const int tid = threadIdx.y * BX + threadIdx.x;

    // Phase-shifted weight pairs:
    // phase0: {w0,w1},{w2,w3},{w4,w5},{w6,0}
    // phase1: {0,w0},{w1,w2},{w3,w4},{w5,w6}
    if (tid < KS * 8) {
        int ky = tid >> 3;
        int r  = tid & 7;
        int ph = r >> 2;
        int j  = r & 3;
        float lo, hi;
        if (ph == 0) {
            lo = W[ky * KS + 2 * j];
            hi = (2 * j + 1 < KS) ? W[ky * KS + 2 * j + 1] : 0.0f;
        } else {
            lo = (2 * j - 1 >= 0) ? W[ky * KS + 2 * j - 1] : 0.0f;
            hi = W[ky * KS + 2 * j];
        }
        s_wp[ky][ph][j] = make_float2(lo, hi);
    }

    const int tileX0 = blockIdx.x * TILE_W;
    const int yBase  = blockIdx.y * YSPAN;
    const int b      = blockIdx.z;
    const float* Xb  = X + (size_t)b * IMG * IMG;
    float* outb      = out + (size_t)b * IMG * IMG;

    const int gx0 = tileX0 - 4;           // 16B-aligned halo start
    const int lx  = threadIdx.x * TX;     // local output col (multiple of 4)
    const int ly  = threadIdx.y * TY;     // local output row

    // Prologue: load chunk 0
    issue_chunk(s_buf[0], Xb, gx0, yBase - PAD, tid);

    for (int c = 0; c < NCHUNK; ++c) {
        // Issue next chunk into the other buffer
        if (c + 1 < NCHUNK)
            issue_chunk(s_buf[(c + 1) & 1], Xb, gx0,
                        yBase + (c + 1) * CHUNK_H - PAD, tid);

        // Wait for chunk c's data
        if (c + 1 < NCHUNK) cp_wait_group<1>();
        else                cp_wait_group<0>();
        __syncthreads();

        const float* buf = s_buf[c & 1];

        ull acc[TY][TX];
#pragma unroll
        for (int ry = 0; ry < TY; ++ry)
#pragma unroll
            for (int ox = 0; ox < TX; ++ox) acc[ry][ox] = 0ull;

#pragma unroll
        for (int ky = 0; ky < KS; ++ky) {
            ull wp0[4], wp1[4];
            const ull* wr0 = reinterpret_cast<const ull*>(&s_wp[ky][0][0]);
            const ull* wr1 = reinterpret_cast<const ull*>(&s_wp[ky][1][0]);
#pragma unroll
            for (int j = 0; j < 4; ++j) { wp0[j] = wr0[j]; wp1[j] = wr1[j]; }

#pragma unroll
            for (int ry = 0; ry < TY; ++ry) {
                // Window: smem cols lx..lx+11 (12 floats, 3 aligned float4).
                // smem col c maps to gx = tileX0 - 4 + c.
                // Output ox taps cols lx+ox+1 .. lx+ox+7.
                const float4* rowp = reinterpret_cast<const float4*>(
                    &buf[(ly + ry + ky) * PITCH + lx]);
                float4 A = rowp[0];
                float4 Bv = rowp[1];
                float4 C = rowp[2];
                ull p0 = pack2(A.x, A.y);
                ull p1 = pack2(A.z, A.w);
                ull p2 = pack2(Bv.x, Bv.y);
                ull p3 = pack2(Bv.z, Bv.w);
                ull p4 = pack2(C.x, C.y);
                ull p5 = pack2(C.z, C.w);

                // ox=0: phase1 over p0..p3
                ffma2(acc[ry][0], p0, wp1[0]); ffma2(acc[ry][0], p1, wp1[1]);
                ffma2(acc[ry][0], p2, wp1[2]); ffma2(acc[ry][0], p3, wp1[3]);
                // ox=1: phase0 over p1..p4
                ffma2(acc[ry][1], p1, wp0[0]); ffma2(acc[ry][1], p2, wp0[1]);
                ffma2(acc[ry][1], p3, wp0[2]); ffma2(acc[ry][1], p4, wp0[3]);
                // ox=2: phase1 over p1..p4
                ffma2(acc[ry][2], p1, wp1[0]); ffma2(acc[ry][2], p2, wp1[1]);
                ffma2(acc[ry][2], p3, wp1[2]); ffma2(acc[ry][2], p4, wp1[3]);
                // ox=3: phase0 over p2..p5
                ffma2(acc[ry][3], p2, wp0[0]); ffma2(acc[ry][3], p3, wp0[1]);
                ffma2(acc[ry][3], p4, wp0[2]); ffma2(acc[ry][3], p5, wp0[3]);
            }
        }

        // Store chunk results (aligned float4)
        const int ox0 = tileX0 + lx;
        const int oy0 = yBase + c * CHUNK_H + ly;
#pragma unroll
        for (int ry = 0; ry < TY; ++ry) {
            float4 v;
            float lo, hi;
            unpack2(acc[ry][0], lo, hi); v.x = lo + hi;
            unpack2(acc[ry][1], lo, hi); v.y = lo + hi;
            unpack2(acc[ry][2], lo, hi); v.z = lo + hi;
            unpack2(acc[ry][3], lo, hi); v.w = lo + hi;
            *reinterpret_cast<float4*>(&outb[(size_t)(oy0 + ry) * IMG + ox0]) = v;
        }

        // All reads of buf done before it is refilled at iteration c+1
        __syncthreads();
    }
}

extern "C" void kernel_launch(void* const* d_in, const int* in_sizes, int n_in,
                              void* d_out, int out_size) {
    const float* X = (const float*)d_in[0];
    const float* W = (const float*)d_in[1];
    float* out = (float*)d_out;

    dim3 block(BX, BY);
    dim3 grid(IMG / TILE_W, YGROUPS, 64);
    conv7x7_kernel<<<grid, block>>>(X, W, out);
}